// round 17
// baseline (speedup 1.0000x reference)
#include <cuda_runtime.h>
#include <cuda_bf16.h>
#include <cuda_fp16.h>
#include <cstdint>

#define N_NODES 100000
#define N_EDGES 1280000
#define D 64
#define NB_SCAN 98            // ceil(100000 / 1024)
#define TC_BLOCKS 782         // ceil(100000 / 128)
#define PITCH 72              // smem row pitch in bf16 (144B) -> conflict-free frags

// ---------------------------------------------------------------------------
// Scratch (__device__ globals; zero-initialized at module load)
__device__ uint4  g_y4u[N_NODES * 8];   // x @ W_l^T in fp16 (8 halves per uint4)
__device__ uint4  g_r4u[N_NODES * 8];   // x @ W_r^T + b in fp16 (8 halves/uint4)
__device__ float4 g_h4[N_NODES * 16];   // layer-1 output (fp32)
__device__ int    g_hist[N_NODES];      // re-zeroed by gather L1
__device__ __align__(16) int g_rank[N_EDGES];  // per-edge slot in dst segment
__device__ int    g_scanpub[NB_SCAN];   // re-zeroed by gather L1
__device__ int    g_off[N_NODES + 1];
__device__ __align__(16) int g_srcsorted[N_EDGES];
// Pre-split weights: rows n: n<64 -> Wl[n], n>=64 -> Wr[n-64]; [layer][n*64+k]
__device__ __nv_bfloat16 g_Bh[2][128 * 64];
__device__ __nv_bfloat16 g_Bl[2][128 * 64];

// ---------------------------------------------------------------------------
// Warp-uniform edge dtype probe: int64 interp valid iff 32 samples in range.
__device__ __forceinline__ int detect64(const void* ei) {
    const long long* p = (const long long*)ei;
    int lane = threadIdx.x & 31;
    long long v = __ldg(&p[lane * 317]);
    return __all_sync(0xFFFFFFFFu, v >= 0 && v < N_NODES);
}

// ---------------------------------------------------------------------------
// Histogram of dst + rank capture (8 edges/thread, MLP=8). Grid: 625x256.
__global__ __launch_bounds__(256) void hist_kernel(const void* __restrict__ ei) {
    const int is64 = detect64(ei);
    const int e0 = (blockIdx.x * 256 + threadIdx.x) * 8;
    int d[8];
    if (is64) {
        const longlong2* p = (const longlong2*)((const long long*)ei + N_EDGES + e0);
        longlong2 a0 = __ldg(p), a1 = __ldg(p + 1), a2 = __ldg(p + 2), a3 = __ldg(p + 3);
        d[0] = (int)a0.x; d[1] = (int)a0.y; d[2] = (int)a1.x; d[3] = (int)a1.y;
        d[4] = (int)a2.x; d[5] = (int)a2.y; d[6] = (int)a3.x; d[7] = (int)a3.y;
    } else {
        const int* p32 = (const int*)ei;
        int4 v0 = __ldg((const int4*)(p32 + N_EDGES) + (e0 >> 2));
        int4 v1 = __ldg((const int4*)(p32 + N_EDGES) + (e0 >> 2) + 1);
        d[0] = v0.x; d[1] = v0.y; d[2] = v0.z; d[3] = v0.w;
        d[4] = v1.x; d[5] = v1.y; d[6] = v1.z; d[7] = v1.w;
    }
    int4 r0, r1;
    r0.x = atomicAdd(&g_hist[d[0]], 1);
    r0.y = atomicAdd(&g_hist[d[1]], 1);
    r0.z = atomicAdd(&g_hist[d[2]], 1);
    r0.w = atomicAdd(&g_hist[d[3]], 1);
    r1.x = atomicAdd(&g_hist[d[4]], 1);
    r1.y = atomicAdd(&g_hist[d[5]], 1);
    r1.z = atomicAdd(&g_hist[d[6]], 1);
    r1.w = atomicAdd(&g_hist[d[7]], 1);
    *(int4*)(g_rank + e0)     = r0;
    *(int4*)(g_rank + e0 + 4) = r1;
}

// ---------------------------------------------------------------------------
// Single-kernel exclusive scan (98 blocks): publish block totals, lookback sum.
// All 98 blocks co-resident (<< 148 SMs) so spinning cannot deadlock.
__global__ __launch_bounds__(256) void scan_kernel() {
    __shared__ int warp_sums[8];
    __shared__ int base_sh;
    const int b = blockIdx.x, t = threadIdx.x;
    const int base = b * 1024 + t * 4;
    int v0 = (base + 0 < N_NODES) ? g_hist[base + 0] : 0;
    int v1 = (base + 1 < N_NODES) ? g_hist[base + 1] : 0;
    int v2 = (base + 2 < N_NODES) ? g_hist[base + 2] : 0;
    int v3 = (base + 3 < N_NODES) ? g_hist[base + 3] : 0;
    int s0 = v0, s1 = s0 + v1, s2 = s1 + v2, s3 = s2 + v3;
    const int lane = t & 31, w = t >> 5;
    int inc = s3;
    #pragma unroll
    for (int off = 1; off < 32; off <<= 1) {
        int n_ = __shfl_up_sync(0xFFFFFFFFu, inc, off);
        if (lane >= off) inc += n_;
    }
    if (lane == 31) warp_sums[w] = inc;
    __syncthreads();
    if (t < 8) {
        int ws = warp_sums[t];
        #pragma unroll
        for (int off = 1; off < 8; off <<= 1) {
            int n_ = __shfl_up_sync(0xFFu, ws, off);
            if ((int)t >= off) ws += n_;
        }
        warp_sums[t] = ws;
    }
    __syncthreads();
    if (t == 0) {
        base_sh = 0;
        atomicExch(&g_scanpub[b], warp_sums[7] + 1);
    }
    __syncthreads();
    for (int i = t; i < b; i += 256) {
        int v;
        do { v = atomicAdd(&g_scanpub[i], 0); } while (v == 0);
        atomicAdd(&base_sh, v - 1);
    }
    __syncthreads();
    const int blk_base = base_sh;
    int warp_prefix = (w > 0) ? warp_sums[w - 1] : 0;
    int te = blk_base + warp_prefix + inc - s3;
    if (base + 0 < N_NODES) g_off[base + 0] = te;
    if (base + 1 < N_NODES) g_off[base + 1] = te + s0;
    if (base + 2 < N_NODES) g_off[base + 2] = te + s1;
    if (base + 3 < N_NODES) g_off[base + 3] = te + s2;
    if (b == NB_SCAN - 1 && t == 0) g_off[N_NODES] = N_EDGES;
}

// ---------------------------------------------------------------------------
// Placement: atomic-free, pos = off[dst] + rank. 8 edges/thread. 625 blocks.
__global__ __launch_bounds__(256) void place_kernel(const void* __restrict__ ei) {
    const int is64 = detect64(ei);
    const int e0 = (blockIdx.x * 256 + threadIdx.x) * 8;
    int s[8], d[8];
    if (is64) {
        const longlong2* ps = (const longlong2*)((const long long*)ei + e0);
        const longlong2* pd = (const longlong2*)((const long long*)ei + N_EDGES + e0);
        longlong2 sa0 = __ldg(ps), sa1 = __ldg(ps + 1), sa2 = __ldg(ps + 2), sa3 = __ldg(ps + 3);
        longlong2 da0 = __ldg(pd), da1 = __ldg(pd + 1), da2 = __ldg(pd + 2), da3 = __ldg(pd + 3);
        s[0] = (int)sa0.x; s[1] = (int)sa0.y; s[2] = (int)sa1.x; s[3] = (int)sa1.y;
        s[4] = (int)sa2.x; s[5] = (int)sa2.y; s[6] = (int)sa3.x; s[7] = (int)sa3.y;
        d[0] = (int)da0.x; d[1] = (int)da0.y; d[2] = (int)da1.x; d[3] = (int)da1.y;
        d[4] = (int)da2.x; d[5] = (int)da2.y; d[6] = (int)da3.x; d[7] = (int)da3.y;
    } else {
        const int* p32 = (const int*)ei;
        int4 sv0 = __ldg((const int4*)p32 + (e0 >> 2));
        int4 sv1 = __ldg((const int4*)p32 + (e0 >> 2) + 1);
        int4 dv0 = __ldg((const int4*)(p32 + N_EDGES) + (e0 >> 2));
        int4 dv1 = __ldg((const int4*)(p32 + N_EDGES) + (e0 >> 2) + 1);
        s[0] = sv0.x; s[1] = sv0.y; s[2] = sv0.z; s[3] = sv0.w;
        s[4] = sv1.x; s[5] = sv1.y; s[6] = sv1.z; s[7] = sv1.w;
        d[0] = dv0.x; d[1] = dv0.y; d[2] = dv0.z; d[3] = dv0.w;
        d[4] = dv1.x; d[5] = dv1.y; d[6] = dv1.z; d[7] = dv1.w;
    }
    int4 r0 = __ldg((const int4*)(g_rank + e0));
    int4 r1 = __ldg((const int4*)(g_rank + e0 + 4));
    int rr[8] = {r0.x, r0.y, r0.z, r0.w, r1.x, r1.y, r1.z, r1.w};
    #pragma unroll
    for (int i = 0; i < 8; i++)
        g_srcsorted[__ldg(&g_off[d[i]]) + rr[i]] = s[i];
}

// ---------------------------------------------------------------------------
// Pre-split weights into bf16 hi/lo, fused B = [Wl ; Wr] per layer.
__global__ __launch_bounds__(256) void prep_w_kernel(
    const float* __restrict__ W1l, const float* __restrict__ W1r,
    const float* __restrict__ W2l, const float* __restrict__ W2r)
{
    int i = blockIdx.x * 256 + threadIdx.x;    // 0 .. 16383
    if (i >= 2 * 128 * 64) return;
    int layer = i >> 13;
    int rem = i & 8191;
    int n = rem >> 6;
    int k = rem & 63;
    const float* W = layer ? (n < 64 ? W2l : W2r) : (n < 64 ? W1l : W1r);
    float v = __ldg(&W[(n & 63) * 64 + k]);
    __nv_bfloat16 h = __float2bfloat16(v);
    __nv_bfloat16 l = __float2bfloat16(v - __bfloat162float(h));
    g_Bh[layer][rem] = h;
    g_Bl[layer][rem] = l;
}

// ---------------------------------------------------------------------------
// mma.sync m16n8k16 bf16 -> f32
__device__ __forceinline__ void mma16816(float* c,
                                         uint32_t a0, uint32_t a1, uint32_t a2, uint32_t a3,
                                         uint32_t b0, uint32_t b1) {
    asm volatile(
        "mma.sync.aligned.m16n8k16.row.col.f32.bf16.bf16.f32 "
        "{%0,%1,%2,%3}, {%4,%5,%6,%7}, {%8,%9}, {%0,%1,%2,%3};"
        : "+f"(c[0]), "+f"(c[1]), "+f"(c[2]), "+f"(c[3])
        : "r"(a0), "r"(a1), "r"(a2), "r"(a3), "r"(b0), "r"(b1));
}

// ---------------------------------------------------------------------------
// Tensor-core transform: per CTA 128 nodes (M) x 128 outs (N = Y|R), K=64.
// 3-term bf16 split: D = Xh*Wh + Xh*Wl + Xl*Wh, fp32 register accumulators.
// Y and R both written as fp16 (half2 pairs); R gets +bias (in fp32) first.
__global__ __launch_bounds__(256)
void transform_mma_kernel(const float4* __restrict__ X,
                          const float* __restrict__ b,
                          int layer, int use_h)
{
    extern __shared__ __nv_bfloat16 sm[];
    __nv_bfloat16* Ah = sm;
    __nv_bfloat16* Al = sm + 128 * PITCH;
    __nv_bfloat16* Bh = sm + 2 * 128 * PITCH;
    __nv_bfloat16* Bl = sm + 3 * 128 * PITCH;

    const int tid = threadIdx.x;
    const int node0 = blockIdx.x * 128;
    const float4* Xv = use_h ? (const float4*)g_h4 : X;

    // Load + split X tile (128 rows x 16 float4 chunks)
    #pragma unroll
    for (int i = tid; i < 2048; i += 256) {
        int n = i >> 4, c = i & 15;
        int gn = node0 + n;
        float4 v = make_float4(0.f, 0.f, 0.f, 0.f);
        if (gn < N_NODES) v = __ldg(Xv + (size_t)gn * 16 + c);
        __nv_bfloat16 hx = __float2bfloat16(v.x), hy = __float2bfloat16(v.y);
        __nv_bfloat16 hz = __float2bfloat16(v.z), hw = __float2bfloat16(v.w);
        __nv_bfloat162 h01, h23, l01, l23;
        h01.x = hx; h01.y = hy; h23.x = hz; h23.y = hw;
        l01.x = __float2bfloat16(v.x - __bfloat162float(hx));
        l01.y = __float2bfloat16(v.y - __bfloat162float(hy));
        l23.x = __float2bfloat16(v.z - __bfloat162float(hz));
        l23.y = __float2bfloat16(v.w - __bfloat162float(hw));
        int base = n * PITCH + c * 4;
        *(__nv_bfloat162*)(Ah + base)     = h01;
        *(__nv_bfloat162*)(Ah + base + 2) = h23;
        *(__nv_bfloat162*)(Al + base)     = l01;
        *(__nv_bfloat162*)(Al + base + 2) = l23;
    }

    // Copy pre-split weights into pitched smem
    {
        const uint32_t* bhp = (const uint32_t*)g_Bh[layer];
        const uint32_t* blp = (const uint32_t*)g_Bl[layer];
        #pragma unroll
        for (int i = tid; i < 4096; i += 256) {
            int n = i >> 5, kp = (i & 31) * 2;
            *(uint32_t*)(Bh + n * PITCH + kp) = __ldg(bhp + i);
            *(uint32_t*)(Bl + n * PITCH + kp) = __ldg(blp + i);
        }
    }
    __syncthreads();

    const int w = tid >> 5, lane = tid & 31;
    const int g = lane >> 2, t = lane & 3;

    float acc[16][4];
    #pragma unroll
    for (int nt = 0; nt < 16; nt++)
        #pragma unroll
        for (int j = 0; j < 4; j++) acc[nt][j] = 0.f;

    const __nv_bfloat16* Aterm[3] = {Ah, Ah, Al};
    const __nv_bfloat16* Bterm[3] = {Bh, Bl, Bh};

    #pragma unroll
    for (int term = 0; term < 3; term++) {
        const __nv_bfloat16* A_ = Aterm[term];
        const __nv_bfloat16* B_ = Bterm[term];
        #pragma unroll
        for (int kk = 0; kk < 4; kk++) {
            const __nv_bfloat16* ar = A_ + (w * 16 + g) * PITCH + kk * 16 + t * 2;
            uint32_t a0 = *(const uint32_t*)ar;
            uint32_t a1 = *(const uint32_t*)(ar + 8 * PITCH);
            uint32_t a2 = *(const uint32_t*)(ar + 8);
            uint32_t a3 = *(const uint32_t*)(ar + 8 * PITCH + 8);
            #pragma unroll
            for (int nt = 0; nt < 16; nt++) {
                const __nv_bfloat16* br = B_ + (nt * 8 + g) * PITCH + kk * 16 + t * 2;
                uint32_t b0 = *(const uint32_t*)br;
                uint32_t b1 = *(const uint32_t*)(br + 8);
                mma16816(acc[nt], a0, a1, a2, a3, b0, b1);
            }
        }
    }

    // Epilogue: c0,c1 -> (row g, cols t*2..+1); c2,c3 -> (row g+8)
    const int row0 = node0 + w * 16 + g;
    const int row1 = row0 + 8;
    uint32_t* Yh = (uint32_t*)g_y4u;      // half2 slots, 32 per node
    uint32_t* Rh = (uint32_t*)g_r4u;      // half2 slots, 32 per node
    #pragma unroll
    for (int nt = 0; nt < 16; nt++) {
        int col = nt * 8 + t * 2;
        if (nt < 8) {
            int hslot = col >> 1;         // = nt*4 + t
            __half2 h01 = __floats2half2_rn(acc[nt][0], acc[nt][1]);
            __half2 h23 = __floats2half2_rn(acc[nt][2], acc[nt][3]);
            if (row0 < N_NODES) Yh[(size_t)row0 * 32 + hslot] = *(uint32_t*)&h01;
            if (row1 < N_NODES) Yh[(size_t)row1 * 32 + hslot] = *(uint32_t*)&h23;
        } else {
            int rc = col - 64;
            int hslot = rc >> 1;
            float2 bb = __ldg((const float2*)(b + rc));
            __half2 h01 = __floats2half2_rn(acc[nt][0] + bb.x, acc[nt][1] + bb.y);
            __half2 h23 = __floats2half2_rn(acc[nt][2] + bb.x, acc[nt][3] + bb.y);
            if (row0 < N_NODES) Rh[(size_t)row0 * 32 + hslot] = *(uint32_t*)&h01;
            if (row1 < N_NODES) Rh[(size_t)row1 * 32 + hslot] = *(uint32_t*)&h23;
        }
    }
}

// ---------------------------------------------------------------------------
// Gather-aggregate + combine. 8 lanes per node, 8 columns (one uint4 of fp16).
// QUAD edge processing: 1 int4 index load + 4 row loads + 2-level HADD2 tree.
// Layer 1 re-zeroes hist/scanpub for the next graph replay.
__global__ __launch_bounds__(256) void gather_combine_kernel(
    float4* __restrict__ Out, int layer)
{
    int idx = blockIdx.x * 256 + threadIdx.x;   // exactly N_NODES*8
    int n = idx >> 3;
    int c = idx & 7;
    int beg = __ldg(&g_off[n]);
    int end = __ldg(&g_off[n + 1]);

    float a0 = 0.f, a1 = 0.f, a2 = 0.f, a3 = 0.f;
    float a4 = 0.f, a5 = 0.f, a6 = 0.f, a7 = 0.f;

    int e = beg;
    // scalar head until e is 4-aligned (int4 index loads need 16B alignment)
    while ((e & 3) && e < end) {
        int s = __ldg(&g_srcsorted[e]);
        uint4 u = __ldg(&g_y4u[s * 8 + c]);
        float2 f0 = __half22float2(*(__half2*)&u.x);
        float2 f1 = __half22float2(*(__half2*)&u.y);
        float2 f2 = __half22float2(*(__half2*)&u.z);
        float2 f3 = __half22float2(*(__half2*)&u.w);
        a0 += f0.x; a1 += f0.y; a2 += f1.x; a3 += f1.y;
        a4 += f2.x; a5 += f2.y; a6 += f3.x; a7 += f3.y;
        e++;
    }
    // quad loop: 2-level fp16 tree sum, then one fp32 accumulate
    for (; e + 4 <= end; e += 4) {
        int4 ss = __ldg((const int4*)(g_srcsorted + e));
        uint4 u0 = __ldg(&g_y4u[ss.x * 8 + c]);
        uint4 u1 = __ldg(&g_y4u[ss.y * 8 + c]);
        uint4 u2 = __ldg(&g_y4u[ss.z * 8 + c]);
        uint4 u3 = __ldg(&g_y4u[ss.w * 8 + c]);
        __half2 q0 = __hadd2(__hadd2(*(__half2*)&u0.x, *(__half2*)&u1.x),
                             __hadd2(*(__half2*)&u2.x, *(__half2*)&u3.x));
        __half2 q1 = __hadd2(__hadd2(*(__half2*)&u0.y, *(__half2*)&u1.y),
                             __hadd2(*(__half2*)&u2.y, *(__half2*)&u3.y));
        __half2 q2 = __hadd2(__hadd2(*(__half2*)&u0.z, *(__half2*)&u1.z),
                             __hadd2(*(__half2*)&u2.z, *(__half2*)&u3.z));
        __half2 q3 = __hadd2(__hadd2(*(__half2*)&u0.w, *(__half2*)&u1.w),
                             __hadd2(*(__half2*)&u2.w, *(__half2*)&u3.w));
        float2 f0 = __half22float2(q0);
        float2 f1 = __half22float2(q1);
        float2 f2 = __half22float2(q2);
        float2 f3 = __half22float2(q3);
        a0 += f0.x; a1 += f0.y; a2 += f1.x; a3 += f1.y;
        a4 += f2.x; a5 += f2.y; a6 += f3.x; a7 += f3.y;
    }
    // scalar tail
    for (; e < end; e++) {
        int s = __ldg(&g_srcsorted[e]);
        uint4 u = __ldg(&g_y4u[s * 8 + c]);
        float2 f0 = __half22float2(*(__half2*)&u.x);
        float2 f1 = __half22float2(*(__half2*)&u.y);
        float2 f2 = __half22float2(*(__half2*)&u.z);
        float2 f3 = __half22float2(*(__half2*)&u.w);
        a0 += f0.x; a1 += f0.y; a2 += f1.x; a3 += f1.y;
        a4 += f2.x; a5 += f2.y; a6 += f3.x; a7 += f3.y;
    }

    float invd = 1.f / fmaxf((float)(end - beg), 1.f);
    uint4 ru = __ldg(&g_r4u[n * 8 + c]);
    float2 r0 = __half22float2(*(__half2*)&ru.x);
    float2 r1 = __half22float2(*(__half2*)&ru.y);
    float2 r2 = __half22float2(*(__half2*)&ru.z);
    float2 r3 = __half22float2(*(__half2*)&ru.w);
    float4 o0 = make_float4(a0 * invd + r0.x, a1 * invd + r0.y,
                            a2 * invd + r1.x, a3 * invd + r1.y);
    float4 o1 = make_float4(a4 * invd + r2.x, a5 * invd + r2.y,
                            a6 * invd + r3.x, a7 * invd + r3.y);
    if (layer == 1) {
        o0.x = fmaxf(o0.x, 0.f); o0.y = fmaxf(o0.y, 0.f);
        o0.z = fmaxf(o0.z, 0.f); o0.w = fmaxf(o0.w, 0.f);
        o1.x = fmaxf(o1.x, 0.f); o1.y = fmaxf(o1.y, 0.f);
        o1.z = fmaxf(o1.z, 0.f); o1.w = fmaxf(o1.w, 0.f);
        g_h4[n * 16 + c * 2]     = o0;
        g_h4[n * 16 + c * 2 + 1] = o1;
        if (c == 0) g_hist[n] = 0;
        if (blockIdx.x == 0 && threadIdx.x < NB_SCAN) g_scanpub[threadIdx.x] = 0;
    } else {
        Out[n * 16 + c * 2]     = o0;
        Out[n * 16 + c * 2 + 1] = o1;
    }
}

// ---------------------------------------------------------------------------
extern "C" void kernel_launch(void* const* d_in, const int* in_sizes, int n_in,
                              void* d_out, int out_size) {
    const float* x   = (const float*)d_in[0];
    const void*  ei  = d_in[1];
    const float* W1l = (const float*)d_in[2];
    const float* b1  = (const float*)d_in[3];
    const float* W1r = (const float*)d_in[4];
    const float* W2l = (const float*)d_in[5];
    const float* b2  = (const float*)d_in[6];
    const float* W2r = (const float*)d_in[7];

    const int SMEM_BYTES = 4 * 128 * PITCH * 2;   // 73728
    static cudaStream_t s2 = nullptr;
    static cudaEvent_t evFork = nullptr, evJoin = nullptr;
    if (!s2) {
        cudaStreamCreateWithFlags(&s2, cudaStreamNonBlocking);
        cudaEventCreateWithFlags(&evFork, cudaEventDisableTiming);
        cudaEventCreateWithFlags(&evJoin, cudaEventDisableTiming);
        cudaFuncSetAttribute(transform_mma_kernel,
                             cudaFuncAttributeMaxDynamicSharedMemorySize, SMEM_BYTES);
    }

    const int GG = (N_NODES * 8) / 256;     // 3125 (exact)
    const int EG8 = N_EDGES / 2048;         // 625 blocks (8 edges/thread, exact)

    // Fork: weight prep + layer-1 transform concurrent with edge sort.
    cudaEventRecord(evFork, 0);
    cudaStreamWaitEvent(s2, evFork, 0);
    prep_w_kernel<<<64, 256, 0, s2>>>(W1l, W1r, W2l, W2r);
    transform_mma_kernel<<<TC_BLOCKS, 256, SMEM_BYTES, s2>>>((const float4*)x, b1, 0, 0);
    cudaEventRecord(evJoin, s2);

    // Edge sort pipeline (stream 0); hist/scanpub zeroed by prior gather L1
    hist_kernel<<<EG8, 256>>>(ei);
    scan_kernel<<<NB_SCAN, 256>>>();
    place_kernel<<<EG8, 256>>>(ei);

    // Join, then aggregate
    cudaStreamWaitEvent(0, evJoin, 0);
    gather_combine_kernel<<<GG, 256>>>(nullptr, 1);

    // Layer 2
    transform_mma_kernel<<<TC_BLOCKS, 256, SMEM_BYTES>>>(nullptr, b2, 1, 1);
    gather_combine_kernel<<<GG, 256>>>((float4*)d_out, 2);
}